// round 1
// baseline (speedup 1.0000x reference)
#include <cuda_runtime.h>

#define N_NODES 2000
#define N_EDGES 16000
#define BB 4
#define L1D 12
#define IN_DIM 16
#define REF 32
#define HID 32
#define OUTD 16
#define NB (N_NODES*BB)   // 8000

// ---------------- scratch (device globals; no allocation) ----------------
__device__ float g_state[NB*L1D*HID];   // [n][b][l][h]
__device__ float g_A[NB*2048];          // A[nb][k*32+h], k=0..63 (b_metaW folded in)
__device__ float g_Bm[NB*2048];         // Bm[nb][k*32+h]
__device__ float g_P1[NB*L1D*HID];      // state @ A1
__device__ float g_P4[NB*L1D*HID];      // state @ B2
__device__ float g_mbs[NB*HID];
__device__ float g_mbd[NB*HID];
__device__ int   g_counts[N_NODES];
__device__ int   g_offsets[N_NODES+1];
__device__ int   g_cursor[N_NODES];
__device__ int   g_sorted[N_EDGES];

// ---------------- fast exp (FMA pipe, avoids MUFU bottleneck) ----------------
__device__ __forceinline__ float fast_exp(float x) {
    float t = x * 1.4426950408889634f;          // x * log2(e)
    t = fminf(fmaxf(t, -126.0f), 126.0f);
    float fi = floorf(t);
    float f  = t - fi;                          // f in [0,1)
    // 2^f Taylor (degree 6): max rel err ~1.5e-5
    float p = 1.5403530e-4f;
    p = fmaf(p, f, 1.3333558e-3f);
    p = fmaf(p, f, 9.6181291e-3f);
    p = fmaf(p, f, 5.5504109e-2f);
    p = fmaf(p, f, 2.4022651e-1f);
    p = fmaf(p, f, 6.9314718e-1f);
    p = fmaf(p, f, 1.0f);
    int ei = (int)fi;
    float s = __int_as_float((ei + 127) << 23);
    return p * s;
}

// ---------------- K1: state = x @ W_in + b_in  (node-major) ----------------
__global__ void k_state(const float* __restrict__ x, const float* __restrict__ W_in,
                        const float* __restrict__ b_in) {
    int n = blockIdx.x;
    __shared__ float xs[BB*L1D*IN_DIM];   // 768
    __shared__ float ws[IN_DIM*HID];      // 512
    __shared__ float bs[HID];
    int t = threadIdx.x;   // 256
    for (int i = t; i < IN_DIM*HID; i += 256) ws[i] = W_in[i];
    if (t < HID) bs[t] = b_in[t];
    for (int i = t; i < BB*L1D*IN_DIM; i += 256) {
        int bl = i / IN_DIM, ii = i % IN_DIM;
        int b = bl / L1D, l = bl % L1D;
        xs[i] = x[((b*L1D + l)*N_NODES + n)*IN_DIM + ii];
    }
    __syncthreads();
    for (int o = t; o < BB*L1D*HID; o += 256) {
        int h = o % HID, bl = o / HID;
        float acc = bs[h];
        #pragma unroll
        for (int i = 0; i < IN_DIM; i++)
            acc = fmaf(xs[bl*IN_DIM + i], ws[i*HID + h], acc);
        g_state[n*(BB*L1D*HID) + o] = acc;   // o = (b*L1D+l)*HID+h
    }
}

// ---------------- K2: per-node hypernetwork GEMM  [8000x32]@[32x4096] ----------------
// g_A[nb][c]  = b_metaW[c] + sum_r mk[n,b,r]*W_metaW[r,c]
// g_Bm[nb][c] =              sum_r mk[n,b,r]*W_metaW[r+32,c]
__global__ void k_meta(const float* __restrict__ mk, const float* __restrict__ W,
                       const float* __restrict__ bW) {
    const int NBT = 32, CT = 128;
    int nb0 = blockIdx.x * NBT;
    int c0  = blockIdx.y * CT;
    __shared__ float mks[NBT][REF];
    __shared__ float wA[REF][CT];
    __shared__ float wB[REF][CT];
    int t = threadIdx.x;   // 256
    for (int i = t; i < NBT*REF; i += 256) {
        int row = i / REF, r = i % REF;
        int nb = nb0 + row, n = nb >> 2, b = nb & 3;
        mks[row][r] = mk[(b*N_NODES + n)*REF + r];
    }
    for (int i = t; i < REF*CT; i += 256) {
        int r = i / CT, c = i % CT;
        wA[r][c] = W[r*2048 + c0 + c];
        wB[r][c] = W[(r + REF)*2048 + c0 + c];
    }
    __syncthreads();
    int tc = t & 15;          // col group
    int tr = t >> 4;          // row pair
    int row0 = tr * 2, col0 = tc * 8;
    float accA[2][8], accB[2][8];
    #pragma unroll
    for (int i = 0; i < 2; i++)
        #pragma unroll
        for (int j = 0; j < 8; j++) { accA[i][j] = 0.f; accB[i][j] = 0.f; }
    for (int r = 0; r < REF; r++) {
        float a0 = mks[row0][r], a1 = mks[row0+1][r];
        #pragma unroll
        for (int j = 0; j < 8; j++) {
            float w  = wA[r][col0 + j];
            float w2 = wB[r][col0 + j];
            accA[0][j] = fmaf(a0, w,  accA[0][j]);
            accA[1][j] = fmaf(a1, w,  accA[1][j]);
            accB[0][j] = fmaf(a0, w2, accB[0][j]);
            accB[1][j] = fmaf(a1, w2, accB[1][j]);
        }
    }
    #pragma unroll
    for (int i = 0; i < 2; i++) {
        int nb = nb0 + row0 + i;
        #pragma unroll
        for (int j = 0; j < 8; j++) {
            int c = c0 + col0 + j;
            g_A[nb*2048 + c]  = accA[i][j] + bW[c];
            g_Bm[nb*2048 + c] = accB[i][j];
        }
    }
}

// ---------------- K2b: P1 = state@A1, P4 = state@B2, mbs/mbd ----------------
__global__ void k_pmb(const float* __restrict__ mk, const float* __restrict__ Wmb,
                      const float* __restrict__ bmb) {
    int nb = blockIdx.x, n = nb >> 2, b = nb & 3;
    __shared__ float st[L1D*HID];
    __shared__ float A1[1024];
    __shared__ float B2[1024];
    __shared__ float mks[REF];
    int t = threadIdx.x;  // 128
    {
        const float4* ps = reinterpret_cast<const float4*>(&g_state[nb*L1D*HID]);
        float4* ss = reinterpret_cast<float4*>(st);
        for (int i = t; i < (L1D*HID)/4; i += 128) ss[i] = ps[i];
        const float4* pa = reinterpret_cast<const float4*>(&g_A[nb*2048]);
        const float4* pb = reinterpret_cast<const float4*>(&g_Bm[nb*2048 + 1024]);
        float4* sa = reinterpret_cast<float4*>(A1);
        float4* sb = reinterpret_cast<float4*>(B2);
        for (int i = t; i < 256; i += 128) { sa[i] = pa[i]; sb[i] = pb[i]; }
    }
    if (t < REF) mks[t] = mk[(b*N_NODES + n)*REF + t];
    __syncthreads();
    int h = t & 31, l0 = t >> 5;
    #pragma unroll
    for (int j = 0; j < 3; j++) {
        int l = l0 + 4*j;
        float p1 = 0.f, p4 = 0.f;
        #pragma unroll
        for (int k = 0; k < HID; k++) {
            float s = st[l*HID + k];
            p1 = fmaf(s, A1[k*32 + h], p1);
            p4 = fmaf(s, B2[k*32 + h], p4);
        }
        g_P1[nb*(L1D*HID) + l*32 + h] = p1;
        g_P4[nb*(L1D*HID) + l*32 + h] = p4;
    }
    if (t < HID) {
        float s1 = 0.f, s2 = bmb[t];
        #pragma unroll
        for (int r = 0; r < REF; r++) {
            s1 = fmaf(mks[r], Wmb[r*HID + t], s1);
            s2 = fmaf(mks[r], Wmb[(r + REF)*HID + t], s2);
        }
        g_mbs[nb*HID + t] = s1;
        g_mbd[nb*HID + t] = s2;
    }
}

// ---------------- K3: deterministic counting sort of edges by dst ----------------
__global__ void k_zero() {
    int t = blockIdx.x*blockDim.x + threadIdx.x;
    if (t < N_NODES) g_counts[t] = 0;
}
__global__ void k_hist(const int* __restrict__ dst) {
    int e = blockIdx.x*blockDim.x + threadIdx.x;
    if (e < N_EDGES) atomicAdd(&g_counts[dst[e]], 1);
}
__global__ void k_scan() {
    __shared__ int s[1024];
    int t = threadIdx.x;
    int i0 = 2*t, i1 = 2*t + 1;
    int a0 = (i0 < N_NODES) ? g_counts[i0] : 0;
    int a1 = (i1 < N_NODES) ? g_counts[i1] : 0;
    s[t] = a0 + a1;
    __syncthreads();
    for (int off = 1; off < 1024; off <<= 1) {
        int v = (t >= off) ? s[t - off] : 0;
        __syncthreads();
        s[t] += v;
        __syncthreads();
    }
    int excl = s[t] - (a0 + a1);
    if (i0 < N_NODES) { g_offsets[i0] = excl;      g_cursor[i0] = excl; }
    if (i1 < N_NODES) { g_offsets[i1] = excl + a0; g_cursor[i1] = excl + a0; }
    if (t == 1023) g_offsets[N_NODES] = s[1023];
}
__global__ void k_scatter(const int* __restrict__ dst) {
    int e = blockIdx.x*blockDim.x + threadIdx.x;
    if (e < N_EDGES) {
        int d = dst[e];
        int pos = atomicAdd(&g_cursor[d], 1);
        g_sorted[pos] = e;
    }
}
// sort each bin by edge id -> fully deterministic accumulation order
__global__ void k_binsort() {
    int d = blockIdx.x*blockDim.x + threadIdx.x;
    if (d >= N_NODES) return;
    int s = g_offsets[d], e = g_offsets[d+1];
    for (int i = s + 1; i < e; i++) {
        int key = g_sorted[i];
        int j = i - 1;
        while (j >= s && g_sorted[j] > key) { g_sorted[j+1] = g_sorted[j]; j--; }
        g_sorted[j+1] = key;
    }
}

// ---------------- K4: fused per-(dst,b) edge attention + softmax + output ----------------
__global__ void k_main(const int* __restrict__ src, const float* __restrict__ W_out,
                       const float* __restrict__ b_out, float* __restrict__ out) {
    int bid = blockIdx.x;
    int n = bid >> 2, b = bid & 3;
    int nbd = n*BB + b;
    __shared__ float B1d[1024];
    __shared__ float std_[L1D*HID];
    __shared__ float P4d[L1D*HID];
    __shared__ float mbd_s[HID];
    __shared__ float sts[L1D*HID];
    __shared__ float A2s[1024];
    __shared__ float P1s[L1D*HID];
    __shared__ float mbs_s[HID];
    __shared__ float wout[HID*OUTD];
    __shared__ float bout[OUTD];
    __shared__ float news[L1D*HID];
    int t = threadIdx.x;  // 128

    {
        const float4* pb = reinterpret_cast<const float4*>(&g_Bm[nbd*2048]);
        float4* sb = reinterpret_cast<float4*>(B1d);
        for (int i = t; i < 256; i += 128) sb[i] = pb[i];
        const float4* ps = reinterpret_cast<const float4*>(&g_state[nbd*L1D*HID]);
        const float4* pp = reinterpret_cast<const float4*>(&g_P4[nbd*L1D*HID]);
        float4* ss = reinterpret_cast<float4*>(std_);
        float4* sp = reinterpret_cast<float4*>(P4d);
        for (int i = t; i < 96; i += 128) { ss[i] = ps[i]; sp[i] = pp[i]; }
    }
    if (t < HID) mbd_s[t] = g_mbd[nbd*HID + t];
    for (int i = t; i < HID*OUTD; i += 128) wout[i] = W_out[i];
    if (t < OUTD) bout[t] = b_out[t];

    int h = t & 31, l0 = t >> 5;
    float num[3] = {0.f, 0.f, 0.f};
    float den[3] = {0.f, 0.f, 0.f};
    int es = g_offsets[n], ee = g_offsets[n+1];
    __syncthreads();

    for (int ei = es; ei < ee; ei++) {
        int e = g_sorted[ei];
        int nbs = src[e]*BB + b;
        // cooperative gather of src-side operands
        {
            const float4* pa = reinterpret_cast<const float4*>(&g_A[nbs*2048 + 1024]);
            float4* sa = reinterpret_cast<float4*>(A2s);
            for (int i = t; i < 256; i += 128) sa[i] = pa[i];
            const float4* ps = reinterpret_cast<const float4*>(&g_state[nbs*L1D*HID]);
            const float4* pp = reinterpret_cast<const float4*>(&g_P1[nbs*L1D*HID]);
            float4* ss = reinterpret_cast<float4*>(sts);
            float4* sp = reinterpret_cast<float4*>(P1s);
            for (int i = t; i < 96; i += 128) { ss[i] = ps[i]; sp[i] = pp[i]; }
        }
        if (t < HID) mbs_s[t] = g_mbs[nbs*HID + t];
        __syncthreads();

        float base = mbs_s[h] + mbd_s[h];
        #pragma unroll
        for (int j = 0; j < 3; j++) {
            int l = l0 + 4*j;
            float a = P1s[l*32 + h] + P4d[l*32 + h] + base;
            #pragma unroll
            for (int k = 0; k < HID; k++) {
                a = fmaf(sts[l*32 + k],  B1d[k*32 + h], a);
                a = fmaf(std_[l*32 + k], A2s[k*32 + h], a);
            }
            float ex = fast_exp(a);
            den[j] += ex;
            num[j] = fmaf(ex, sts[l*32 + h], num[j]);
        }
        __syncthreads();
    }

    #pragma unroll
    for (int j = 0; j < 3; j++) {
        int l = l0 + 4*j;
        float d = den[j];
        news[l*32 + h] = num[j] / (d == 0.f ? 1.f : d);
    }
    __syncthreads();

    for (int oi = t; oi < L1D*OUTD; oi += 128) {
        int l = oi / OUTD, o = oi % OUTD;
        float p = bout[o];
        #pragma unroll
        for (int hh = 0; hh < HID; hh++)
            p = fmaf(news[l*32 + hh], wout[hh*OUTD + o], p);
        out[((b*L1D + l)*N_NODES + n)*OUTD + o] = p;
    }
}

// ---------------- launch ----------------
extern "C" void kernel_launch(void* const* d_in, const int* in_sizes, int n_in,
                              void* d_out, int out_size) {
    const float* long_states = (const float*)d_in[0];   // [B,N,REF]
    const float* short_in    = (const float*)d_in[1];   // [B,L1,N,IN]
    const int*   src         = (const int*)d_in[2];
    const int*   dst         = (const int*)d_in[3];
    const float* W_in        = (const float*)d_in[4];
    const float* b_in        = (const float*)d_in[5];
    const float* W_metaW     = (const float*)d_in[6];
    const float* b_metaW     = (const float*)d_in[7];
    const float* W_metab     = (const float*)d_in[8];
    const float* b_metab     = (const float*)d_in[9];
    const float* W_out       = (const float*)d_in[10];
    const float* b_out       = (const float*)d_in[11];
    float* out = (float*)d_out;

    k_state<<<N_NODES, 256>>>(short_in, W_in, b_in);
    k_meta<<<dim3(NB/32, 2048/128), 256>>>(long_states, W_metaW, b_metaW);
    k_pmb<<<NB, 128>>>(long_states, W_metab, b_metab);

    k_zero<<<(N_NODES + 255)/256, 256>>>();
    k_hist<<<(N_EDGES + 255)/256, 256>>>(dst);
    k_scan<<<1, 1024>>>();
    k_scatter<<<(N_EDGES + 255)/256, 256>>>(dst);
    k_binsort<<<(N_NODES + 255)/256, 256>>>();

    k_main<<<NB, 128>>>(src, W_out, b_out, out);
}

// round 2
// speedup vs baseline: 1.5328x; 1.5328x over previous
#include <cuda_runtime.h>

#define N_NODES 2000
#define N_EDGES 16000
#define BB 4
#define L1D 12
#define IN_DIM 16
#define REF 32
#define HID 32
#define OUTD 16
#define NB (N_NODES*BB)   // 8000

typedef unsigned long long u64;

// ---------------- scratch (device globals; no allocation) ----------------
__device__ float g_state[NB*L1D*HID];   // [n][b][l][h]
__device__ float g_A[NB*2048];          // A[nb][k*32+h], k=0..63 (b_metaW folded in)
__device__ float g_Bm[NB*2048];         // Bm[nb][k*32+h]
__device__ float g_P1[NB*L1D*HID];      // state @ A1
__device__ float g_P4[NB*L1D*HID];      // state @ B2
__device__ float g_mbs[NB*HID];
__device__ float g_mbd[NB*HID];
__device__ int   g_offsets[N_NODES+1];
__device__ int   g_sorted[N_EDGES];

// ---------------- f32x2 packed helpers (Blackwell) ----------------
__device__ __forceinline__ u64 pk2(float lo, float hi) {
    u64 r; asm("mov.b64 %0, {%1,%2};" : "=l"(r) : "f"(lo), "f"(hi)); return r;
}
__device__ __forceinline__ u64 pk2s(float v) { return pk2(v, v); }
__device__ __forceinline__ void upk2(float& lo, float& hi, u64 v) {
    asm("mov.b64 {%0,%1}, %2;" : "=f"(lo), "=f"(hi) : "l"(v));
}
__device__ __forceinline__ u64 fma2(u64 a, u64 b, u64 c) {
    u64 d; asm("fma.rn.f32x2 %0, %1, %2, %3;" : "=l"(d) : "l"(a), "l"(b), "l"(c)); return d;
}
__device__ __forceinline__ u64 add2(u64 a, u64 b) {
    u64 d; asm("add.rn.f32x2 %0, %1, %2;" : "=l"(d) : "l"(a), "l"(b)); return d;
}

// ---------------- K1: state = x @ W_in + b_in  (node-major) ----------------
__global__ void k_state(const float* __restrict__ x, const float* __restrict__ W_in,
                        const float* __restrict__ b_in) {
    int n = blockIdx.x;
    __shared__ float xs[BB*L1D*IN_DIM];   // 768
    __shared__ float ws[IN_DIM*HID];      // 512
    __shared__ float bs[HID];
    int t = threadIdx.x;   // 256
    for (int i = t; i < IN_DIM*HID; i += 256) ws[i] = W_in[i];
    if (t < HID) bs[t] = b_in[t];
    for (int i = t; i < BB*L1D*IN_DIM; i += 256) {
        int bl = i / IN_DIM, ii = i % IN_DIM;
        int b = bl / L1D, l = bl % L1D;
        xs[i] = x[((b*L1D + l)*N_NODES + n)*IN_DIM + ii];
    }
    __syncthreads();
    for (int o = t; o < BB*L1D*HID; o += 256) {
        int h = o % HID, bl = o / HID;
        float acc = bs[h];
        #pragma unroll
        for (int i = 0; i < IN_DIM; i++)
            acc = fmaf(xs[bl*IN_DIM + i], ws[i*HID + h], acc);
        g_state[n*(BB*L1D*HID) + o] = acc;
    }
}

// ---------------- K2: per-node hypernetwork GEMM (f32x2) ----------------
// 128 threads; thread tile = 4 rows x 8 cols on both A and B halves.
__global__ void __launch_bounds__(128) k_meta(const float* __restrict__ mk,
                                              const float* __restrict__ W,
                                              const float* __restrict__ bW) {
    const int NBT = 32, CT = 128;
    int nb0 = blockIdx.x * NBT;
    int c0  = blockIdx.y * CT;
    __shared__ __align__(16) float mks[NBT][REF];
    __shared__ __align__(16) float wA[REF][CT];
    __shared__ __align__(16) float wB[REF][CT];
    int t = threadIdx.x;   // 128
    for (int i = t; i < NBT*REF; i += 128) {
        int row = i / REF, r = i % REF;
        int nb = nb0 + row, n = nb >> 2, b = nb & 3;
        mks[row][r] = mk[(b*N_NODES + n)*REF + r];
    }
    for (int i = t; i < REF*CT/4; i += 128) {
        int r = (i*4) / CT, c = (i*4) % CT;
        *(float4*)&wA[r][c] = *(const float4*)&W[r*2048 + c0 + c];
        *(float4*)&wB[r][c] = *(const float4*)&W[(r + REF)*2048 + c0 + c];
    }
    __syncthreads();
    int tc = t & 15;          // col group (8 cols)
    int tr = t >> 4;          // row group (4 rows)
    int row0 = tr * 4, col0 = tc * 8;
    u64 accA[4][4], accB[4][4];
    #pragma unroll
    for (int i = 0; i < 4; i++)
        #pragma unroll
        for (int j = 0; j < 4; j++) { accA[i][j] = 0ull; accB[i][j] = 0ull; }
    #pragma unroll 8
    for (int r = 0; r < REF; r++) {
        ulonglong2 wa0 = *(const ulonglong2*)&wA[r][col0];
        ulonglong2 wa1 = *(const ulonglong2*)&wA[r][col0+4];
        ulonglong2 wb0 = *(const ulonglong2*)&wB[r][col0];
        ulonglong2 wb1 = *(const ulonglong2*)&wB[r][col0+4];
        #pragma unroll
        for (int i = 0; i < 4; i++) {
            u64 a = pk2s(mks[row0+i][r]);
            accA[i][0] = fma2(a, wa0.x, accA[i][0]);
            accA[i][1] = fma2(a, wa0.y, accA[i][1]);
            accA[i][2] = fma2(a, wa1.x, accA[i][2]);
            accA[i][3] = fma2(a, wa1.y, accA[i][3]);
            accB[i][0] = fma2(a, wb0.x, accB[i][0]);
            accB[i][1] = fma2(a, wb0.y, accB[i][1]);
            accB[i][2] = fma2(a, wb1.x, accB[i][2]);
            accB[i][3] = fma2(a, wb1.y, accB[i][3]);
        }
    }
    ulonglong2 bv0 = *(const ulonglong2*)&bW[c0 + col0];
    ulonglong2 bv1 = *(const ulonglong2*)&bW[c0 + col0 + 4];
    #pragma unroll
    for (int i = 0; i < 4; i++) {
        int nb = nb0 + row0 + i;
        ulonglong2 oa0, oa1, ob0, ob1;
        oa0.x = add2(accA[i][0], bv0.x); oa0.y = add2(accA[i][1], bv0.y);
        oa1.x = add2(accA[i][2], bv1.x); oa1.y = add2(accA[i][3], bv1.y);
        ob0.x = accB[i][0]; ob0.y = accB[i][1];
        ob1.x = accB[i][2]; ob1.y = accB[i][3];
        *(ulonglong2*)&g_A[nb*2048 + c0 + col0]      = oa0;
        *(ulonglong2*)&g_A[nb*2048 + c0 + col0 + 4]  = oa1;
        *(ulonglong2*)&g_Bm[nb*2048 + c0 + col0]     = ob0;
        *(ulonglong2*)&g_Bm[nb*2048 + c0 + col0 + 4] = ob1;
    }
}

// ---------------- K2b: P1 = state@A1, P4 = state@B2, mbs/mbd ----------------
__global__ void k_pmb(const float* __restrict__ mk, const float* __restrict__ Wmb,
                      const float* __restrict__ bmb) {
    int nb = blockIdx.x, n = nb >> 2, b = nb & 3;
    __shared__ float st[L1D*HID];
    __shared__ float A1[1024];
    __shared__ float B2[1024];
    __shared__ float mks[REF];
    int t = threadIdx.x;  // 128
    {
        const float4* ps = reinterpret_cast<const float4*>(&g_state[nb*L1D*HID]);
        float4* ss = reinterpret_cast<float4*>(st);
        for (int i = t; i < (L1D*HID)/4; i += 128) ss[i] = ps[i];
        const float4* pa = reinterpret_cast<const float4*>(&g_A[nb*2048]);
        const float4* pb = reinterpret_cast<const float4*>(&g_Bm[nb*2048 + 1024]);
        float4* sa = reinterpret_cast<float4*>(A1);
        float4* sb = reinterpret_cast<float4*>(B2);
        for (int i = t; i < 256; i += 128) { sa[i] = pa[i]; sb[i] = pb[i]; }
    }
    if (t < REF) mks[t] = mk[(b*N_NODES + n)*REF + t];
    __syncthreads();
    int h = t & 31, l0 = t >> 5;
    #pragma unroll
    for (int j = 0; j < 3; j++) {
        int l = l0 + 4*j;
        float p1 = 0.f, p4 = 0.f;
        #pragma unroll
        for (int k = 0; k < HID; k++) {
            float s = st[l*HID + k];
            p1 = fmaf(s, A1[k*32 + h], p1);
            p4 = fmaf(s, B2[k*32 + h], p4);
        }
        g_P1[nb*(L1D*HID) + l*32 + h] = p1;
        g_P4[nb*(L1D*HID) + l*32 + h] = p4;
    }
    if (t < HID) {
        float s1 = 0.f, s2 = bmb[t];
        #pragma unroll
        for (int r = 0; r < REF; r++) {
            s1 = fmaf(mks[r], Wmb[r*HID + t], s1);
            s2 = fmaf(mks[r], Wmb[(r + REF)*HID + t], s2);
        }
        g_mbs[nb*HID + t] = s1;
        g_mbd[nb*HID + t] = s2;
    }
}

// ---------------- K3: single-block deterministic counting sort by dst ----------------
__global__ void k_sort(const int* __restrict__ dst) {
    __shared__ int cnt[N_NODES];
    __shared__ int sb[1024];
    int t = threadIdx.x;  // 1024
    for (int i = t; i < N_NODES; i += 1024) cnt[i] = 0;
    __syncthreads();
    for (int e = t; e < N_EDGES; e += 1024) atomicAdd(&cnt[dst[e]], 1);
    __syncthreads();
    int i0 = 2*t, i1 = 2*t + 1;
    int a0 = (i0 < N_NODES) ? cnt[i0] : 0;
    int a1 = (i1 < N_NODES) ? cnt[i1] : 0;
    sb[t] = a0 + a1;
    __syncthreads();
    for (int off = 1; off < 1024; off <<= 1) {
        int v = (t >= off) ? sb[t - off] : 0;
        __syncthreads();
        sb[t] += v;
        __syncthreads();
    }
    int excl = sb[t] - (a0 + a1);
    if (i0 < N_NODES) { g_offsets[i0] = excl;      cnt[i0] = excl; }
    if (i1 < N_NODES) { g_offsets[i1] = excl + a0; cnt[i1] = excl + a0; }
    if (t == 1023) g_offsets[N_NODES] = sb[1023];
    __syncthreads();
    for (int e = t; e < N_EDGES; e += 1024) {
        int d = dst[e];
        int pos = atomicAdd(&cnt[d], 1);
        g_sorted[pos] = e;
    }
    __syncthreads();
    for (int d = t; d < N_NODES; d += 1024) {
        int s = g_offsets[d], e2 = g_offsets[d+1];
        for (int i = s + 1; i < e2; i++) {
            int key = g_sorted[i];
            int j = i - 1;
            while (j >= s && g_sorted[j] > key) { g_sorted[j+1] = g_sorted[j]; j--; }
            g_sorted[j+1] = key;
        }
    }
}

// ---------------- K4: one warp per (dst,b); 3l x 4h register tile; f32x2 ----------------
__global__ void __launch_bounds__(32) k_main(const int* __restrict__ src,
                                             const float* __restrict__ W_out,
                                             const float* __restrict__ b_out,
                                             float* __restrict__ out) {
    int bid = blockIdx.x;
    int n = bid >> 2, b = bid & 3;
    int nbd = n*4 + b;
    __shared__ __align__(16) float B1d[1024];     // [k][h]  dst, fixed
    __shared__ __align__(16) float A2s[1024];     // [k][h]  src, per edge
    __shared__ __align__(16) float stds[12*33];   // std_[l][k], bcast-padded
    __shared__ __align__(16) float stsS[12*36];   // sts[l][k], vec-aligned pad
    __shared__ __align__(16) float P1s[12*36];
    __shared__ __align__(16) float P4m[12*36];    // P4d + mbd, fixed
    __shared__ __align__(16) float mbsS[32];
    __shared__ __align__(16) float wout[512];
    __shared__ __align__(16) float news[384];
    int lane = threadIdx.x;
    int lg = lane >> 3, hg = lane & 7, h4 = hg * 4;
    int l0 = lg * 3;

    // prologue: dst-side fixed data
    {
        const float4* pb = (const float4*)&g_Bm[nbd*2048];
        float4* sbp = (float4*)B1d;
        #pragma unroll
        for (int i = lane; i < 256; i += 32) sbp[i] = pb[i];
        for (int i = lane; i < 384; i += 32) {
            int l = i >> 5, k = i & 31;
            stds[l*33 + k] = g_state[nbd*384 + i];
            P4m[l*36 + k] = g_P4[nbd*384 + i] + g_mbd[nbd*32 + k];
        }
        #pragma unroll
        for (int i = lane; i < 128; i += 32)
            ((float4*)wout)[i] = ((const float4*)W_out)[i];
    }
    int es = g_offsets[n], ee = g_offsets[n+1];
    u64 num[3][2], den[3][2];
    #pragma unroll
    for (int j = 0; j < 3; j++) { num[j][0]=num[j][1]=den[j][0]=den[j][1]=0ull; }
    __syncwarp();

    for (int ei = es; ei < ee; ei++) {
        int e = g_sorted[ei];
        int nbs = src[e]*4 + b;
        // stage src-side operands (warp-cooperative)
        {
            const float4* pa = (const float4*)&g_A[nbs*2048 + 1024];
            float4* sa = (float4*)A2s;
            #pragma unroll
            for (int i = lane; i < 256; i += 32) sa[i] = pa[i];
            const float4* ps = (const float4*)&g_state[nbs*384];
            const float4* pp = (const float4*)&g_P1[nbs*384];
            #pragma unroll
            for (int i = lane; i < 96; i += 32) {
                int l = i >> 3, c4 = (i & 7) * 4;
                *(float4*)&stsS[l*36 + c4] = ps[i];
                *(float4*)&P1s[l*36 + c4] = pp[i];
            }
            mbsS[lane] = g_mbs[nbs*32 + lane];
        }
        __syncwarp();

        u64 att[3][2];
        float4 mb4 = *(float4*)&mbsS[h4];
        #pragma unroll
        for (int j = 0; j < 3; j++) {
            int l = l0 + j;
            float4 p1 = *(float4*)&P1s[l*36 + h4];
            float4 p4 = *(float4*)&P4m[l*36 + h4];
            att[j][0] = pk2(p1.x + p4.x + mb4.x, p1.y + p4.y + mb4.y);
            att[j][1] = pk2(p1.z + p4.z + mb4.z, p1.w + p4.w + mb4.w);
        }
        #pragma unroll 16
        for (int k = 0; k < 32; k++) {
            ulonglong2 bb = *(const ulonglong2*)&B1d[k*32 + h4];
            ulonglong2 aa = *(const ulonglong2*)&A2s[k*32 + h4];
            #pragma unroll
            for (int j = 0; j < 3; j++) {
                int l = l0 + j;
                u64 ss = pk2s(stsS[l*36 + k]);
                u64 dd = pk2s(stds[l*33 + k]);
                att[j][0] = fma2(ss, bb.x, att[j][0]);
                att[j][1] = fma2(ss, bb.y, att[j][1]);
                att[j][0] = fma2(dd, aa.x, att[j][0]);
                att[j][1] = fma2(dd, aa.y, att[j][1]);
            }
        }
        #pragma unroll
        for (int j = 0; j < 3; j++) {
            int l = l0 + j;
            float a0,a1,a2,a3;
            upk2(a0, a1, att[j][0]); upk2(a2, a3, att[j][1]);
            float e0 = __expf(a0), e1 = __expf(a1), e2 = __expf(a2), e3 = __expf(a3);
            u64 ep0 = pk2(e0, e1), ep1 = pk2(e2, e3);
            den[j][0] = add2(den[j][0], ep0);
            den[j][1] = add2(den[j][1], ep1);
            float4 sv = *(float4*)&stsS[l*36 + h4];
            num[j][0] = fma2(ep0, pk2(sv.x, sv.y), num[j][0]);
            num[j][1] = fma2(ep1, pk2(sv.z, sv.w), num[j][1]);
        }
        __syncwarp();
    }

    // news = num / den  (den==0 -> 0, matching reference's empty-mailbox path)
    #pragma unroll
    for (int j = 0; j < 3; j++) {
        int l = l0 + j;
        float n0,n1,n2,n3,d0,d1,d2,d3;
        upk2(n0, n1, num[j][0]); upk2(n2, n3, num[j][1]);
        upk2(d0, d1, den[j][0]); upk2(d2, d3, den[j][1]);
        float4 r;
        r.x = __fdividef(n0, d0 == 0.f ? 1.f : d0);
        r.y = __fdividef(n1, d1 == 0.f ? 1.f : d1);
        r.z = __fdividef(n2, d2 == 0.f ? 1.f : d2);
        r.w = __fdividef(n3, d3 == 0.f ? 1.f : d3);
        *(float4*)&news[l*32 + h4] = r;
    }
    __syncwarp();

    // output projection: 12x16 = 192 outputs, 6 per lane
    for (int oi = lane; oi < L1D*OUTD; oi += 32) {
        int l = oi >> 4, o = oi & 15;
        float acc = b_out[o];
        #pragma unroll
        for (int h = 0; h < HID; h++)
            acc = fmaf(news[l*32 + h], wout[h*16 + o], acc);
        out[((b*L1D + l)*N_NODES + n)*OUTD + o] = acc;
    }
}

// ---------------- launch ----------------
extern "C" void kernel_launch(void* const* d_in, const int* in_sizes, int n_in,
                              void* d_out, int out_size) {
    const float* long_states = (const float*)d_in[0];   // [B,N,REF]
    const float* short_in    = (const float*)d_in[1];   // [B,L1,N,IN]
    const int*   src         = (const int*)d_in[2];
    const int*   dst         = (const int*)d_in[3];
    const float* W_in        = (const float*)d_in[4];
    const float* b_in        = (const float*)d_in[5];
    const float* W_metaW     = (const float*)d_in[6];
    const float* b_metaW     = (const float*)d_in[7];
    const float* W_metab     = (const float*)d_in[8];
    const float* b_metab     = (const float*)d_in[9];
    const float* W_out       = (const float*)d_in[10];
    const float* b_out       = (const float*)d_in[11];
    float* out = (float*)d_out;

    k_state<<<N_NODES, 256>>>(short_in, W_in, b_in);
    k_meta<<<dim3(NB/32, 2048/128), 128>>>(long_states, W_metaW, b_metaW);
    k_pmb<<<NB, 128>>>(long_states, W_metab, b_metab);
    k_sort<<<1, 1024>>>(dst);
    k_main<<<NB, 32>>>(src, W_out, b_out, out);
}

// round 4
// speedup vs baseline: 1.6130x; 1.0523x over previous
#include <cuda_runtime.h>

#define N_NODES 2000
#define N_EDGES 16000
#define BB 4
#define L1D 12
#define IN_DIM 16
#define REF 32
#define HID 32
#define OUTD 16
#define NB (N_NODES*BB)   // 8000
#define MAXDEG 64

typedef unsigned long long u64;
typedef unsigned int u32;

// ---------------- scratch (device globals; no allocation) ----------------
__device__ float g_state[NB*L1D*HID];   // [n][b][l][h]
__device__ float g_A[NB*2048];          // A[nb][k*32+h], k=0..63 (b_metaW folded in)
__device__ float g_Bm[NB*2048];         // Bm[nb][k*32+h]
__device__ float g_P1[NB*L1D*HID];      // state @ A1
__device__ float g_P4[NB*L1D*HID];      // state @ B2
__device__ float g_mbs[NB*HID];
__device__ float g_mbd[NB*HID];
__device__ int   g_counts[N_NODES];
__device__ int   g_cursor[N_NODES];
__device__ int   g_offsets[N_NODES+1];
__device__ int   g_sorted[N_EDGES];

// ---------------- f32x2 packed helpers (Blackwell) ----------------
__device__ __forceinline__ u64 pk2(float lo, float hi) {
    u64 r; asm("mov.b64 %0, {%1,%2};" : "=l"(r) : "f"(lo), "f"(hi)); return r;
}
__device__ __forceinline__ u64 pk2s(float v) { return pk2(v, v); }
__device__ __forceinline__ void upk2(float& lo, float& hi, u64 v) {
    asm("mov.b64 {%0,%1}, %2;" : "=f"(lo), "=f"(hi) : "l"(v));
}
__device__ __forceinline__ u64 fma2(u64 a, u64 b, u64 c) {
    u64 d; asm("fma.rn.f32x2 %0, %1, %2, %3;" : "=l"(d) : "l"(a), "l"(b), "l"(c)); return d;
}
__device__ __forceinline__ u64 add2(u64 a, u64 b) {
    u64 d; asm("add.rn.f32x2 %0, %1, %2;" : "=l"(d) : "l"(a), "l"(b)); return d;
}

// ---------------- cp.async helpers ----------------
__device__ __forceinline__ void cpa16(u32 s, const void* g) {
    asm volatile("cp.async.cg.shared.global [%0], [%1], 16;" :: "r"(s), "l"(g));
}
__device__ __forceinline__ void cpcommit() {
    asm volatile("cp.async.commit_group;");
}
template<int N> __device__ __forceinline__ void cpwait() {
    asm volatile("cp.async.wait_group %0;" :: "n"(N));
}

// ---------------- K1: state = x @ W_in + b_in  (node-major); zero hist ----------------
__global__ void k_state(const float* __restrict__ x, const float* __restrict__ W_in,
                        const float* __restrict__ b_in) {
    int n = blockIdx.x;
    __shared__ float xs[BB*L1D*IN_DIM];   // 768
    __shared__ float ws[IN_DIM*HID];      // 512
    __shared__ float bs[HID];
    int t = threadIdx.x;   // 256
    if (t == 0) g_counts[n] = 0;          // zero histogram for the sort
    for (int i = t; i < IN_DIM*HID; i += 256) ws[i] = W_in[i];
    if (t < HID) bs[t] = b_in[t];
    for (int i = t; i < BB*L1D*IN_DIM; i += 256) {
        int bl = i / IN_DIM, ii = i % IN_DIM;
        int b = bl / L1D, l = bl % L1D;
        xs[i] = x[((b*L1D + l)*N_NODES + n)*IN_DIM + ii];
    }
    __syncthreads();
    for (int o = t; o < BB*L1D*HID; o += 256) {
        int h = o % HID, bl = o / HID;
        float acc = bs[h];
        #pragma unroll
        for (int i = 0; i < IN_DIM; i++)
            acc = fmaf(xs[bl*IN_DIM + i], ws[i*HID + h], acc);
        g_state[n*(BB*L1D*HID) + o] = acc;
    }
}

// ---------------- K2: per-node hypernetwork GEMM (f32x2) ----------------
__global__ void __launch_bounds__(128) k_meta(const float* __restrict__ mk,
                                              const float* __restrict__ W,
                                              const float* __restrict__ bW) {
    const int NBT = 32, CT = 128;
    int nb0 = blockIdx.x * NBT;
    int c0  = blockIdx.y * CT;
    __shared__ __align__(16) float mks[NBT][REF];
    __shared__ __align__(16) float wA[REF][CT];
    __shared__ __align__(16) float wB[REF][CT];
    int t = threadIdx.x;   // 128
    for (int i = t; i < NBT*REF; i += 128) {
        int row = i / REF, r = i % REF;
        int nb = nb0 + row, n = nb >> 2, b = nb & 3;
        mks[row][r] = mk[(b*N_NODES + n)*REF + r];
    }
    for (int i = t; i < REF*CT/4; i += 128) {
        int r = (i*4) / CT, c = (i*4) % CT;
        *(float4*)&wA[r][c] = *(const float4*)&W[r*2048 + c0 + c];
        *(float4*)&wB[r][c] = *(const float4*)&W[(r + REF)*2048 + c0 + c];
    }
    __syncthreads();
    int tc = t & 15;
    int tr = t >> 4;
    int row0 = tr * 4, col0 = tc * 8;
    u64 accA[4][4], accB[4][4];
    #pragma unroll
    for (int i = 0; i < 4; i++)
        #pragma unroll
        for (int j = 0; j < 4; j++) { accA[i][j] = 0ull; accB[i][j] = 0ull; }
    #pragma unroll 8
    for (int r = 0; r < REF; r++) {
        ulonglong2 wa0 = *(const ulonglong2*)&wA[r][col0];
        ulonglong2 wa1 = *(const ulonglong2*)&wA[r][col0+4];
        ulonglong2 wb0 = *(const ulonglong2*)&wB[r][col0];
        ulonglong2 wb1 = *(const ulonglong2*)&wB[r][col0+4];
        #pragma unroll
        for (int i = 0; i < 4; i++) {
            u64 a = pk2s(mks[row0+i][r]);
            accA[i][0] = fma2(a, wa0.x, accA[i][0]);
            accA[i][1] = fma2(a, wa0.y, accA[i][1]);
            accA[i][2] = fma2(a, wa1.x, accA[i][2]);
            accA[i][3] = fma2(a, wa1.y, accA[i][3]);
            accB[i][0] = fma2(a, wb0.x, accB[i][0]);
            accB[i][1] = fma2(a, wb0.y, accB[i][1]);
            accB[i][2] = fma2(a, wb1.x, accB[i][2]);
            accB[i][3] = fma2(a, wb1.y, accB[i][3]);
        }
    }
    ulonglong2 bv0 = *(const ulonglong2*)&bW[c0 + col0];
    ulonglong2 bv1 = *(const ulonglong2*)&bW[c0 + col0 + 4];
    #pragma unroll
    for (int i = 0; i < 4; i++) {
        int nb = nb0 + row0 + i;
        ulonglong2 oa0, oa1, ob0, ob1;
        oa0.x = add2(accA[i][0], bv0.x); oa0.y = add2(accA[i][1], bv0.y);
        oa1.x = add2(accA[i][2], bv1.x); oa1.y = add2(accA[i][3], bv1.y);
        ob0.x = accB[i][0]; ob0.y = accB[i][1];
        ob1.x = accB[i][2]; ob1.y = accB[i][3];
        *(ulonglong2*)&g_A[nb*2048 + c0 + col0]      = oa0;
        *(ulonglong2*)&g_A[nb*2048 + c0 + col0 + 4]  = oa1;
        *(ulonglong2*)&g_Bm[nb*2048 + c0 + col0]     = ob0;
        *(ulonglong2*)&g_Bm[nb*2048 + c0 + col0 + 4] = ob1;
    }
}

// ---------------- K2b: P1 = state@A1, P4 = state@B2, mbs/mbd ----------------
__global__ void k_pmb(const float* __restrict__ mk, const float* __restrict__ Wmb,
                      const float* __restrict__ bmb) {
    int nb = blockIdx.x, n = nb >> 2, b = nb & 3;
    __shared__ float st[L1D*HID];
    __shared__ float A1[1024];
    __shared__ float B2[1024];
    __shared__ float mks[REF];
    int t = threadIdx.x;  // 128
    {
        const float4* ps = reinterpret_cast<const float4*>(&g_state[nb*L1D*HID]);
        float4* ss = reinterpret_cast<float4*>(st);
        for (int i = t; i < (L1D*HID)/4; i += 128) ss[i] = ps[i];
        const float4* pa = reinterpret_cast<const float4*>(&g_A[nb*2048]);
        const float4* pb = reinterpret_cast<const float4*>(&g_Bm[nb*2048 + 1024]);
        float4* sa = reinterpret_cast<float4*>(A1);
        float4* sb = reinterpret_cast<float4*>(B2);
        for (int i = t; i < 256; i += 128) { sa[i] = pa[i]; sb[i] = pb[i]; }
    }
    if (t < REF) mks[t] = mk[(b*N_NODES + n)*REF + t];
    __syncthreads();
    int h = t & 31, l0 = t >> 5;
    #pragma unroll
    for (int j = 0; j < 3; j++) {
        int l = l0 + 4*j;
        float p1 = 0.f, p4 = 0.f;
        #pragma unroll
        for (int k = 0; k < HID; k++) {
            float s = st[l*HID + k];
            p1 = fmaf(s, A1[k*32 + h], p1);
            p4 = fmaf(s, B2[k*32 + h], p4);
        }
        g_P1[nb*(L1D*HID) + l*32 + h] = p1;
        g_P4[nb*(L1D*HID) + l*32 + h] = p4;
    }
    if (t < HID) {
        float s1 = 0.f, s2 = bmb[t];
        #pragma unroll
        for (int r = 0; r < REF; r++) {
            s1 = fmaf(mks[r], Wmb[r*HID + t], s1);
            s2 = fmaf(mks[r], Wmb[(r + REF)*HID + t], s2);
        }
        g_mbs[nb*HID + t] = s1;
        g_mbd[nb*HID + t] = s2;
    }
}

// ---------------- K3: parallel deterministic counting sort by dst ----------------
__global__ void k_hist(const int* __restrict__ dst) {
    int e = blockIdx.x*blockDim.x + threadIdx.x;
    if (e < N_EDGES) atomicAdd(&g_counts[dst[e]], 1);
}
__global__ void k_scan() {
    __shared__ int sb[1024];
    int t = threadIdx.x;
    int i0 = 2*t, i1 = 2*t + 1;
    int a0 = (i0 < N_NODES) ? g_counts[i0] : 0;
    int a1 = (i1 < N_NODES) ? g_counts[i1] : 0;
    sb[t] = a0 + a1;
    __syncthreads();
    for (int off = 1; off < 1024; off <<= 1) {
        int v = (t >= off) ? sb[t - off] : 0;
        __syncthreads();
        sb[t] += v;
        __syncthreads();
    }
    int excl = sb[t] - (a0 + a1);
    if (i0 < N_NODES) { g_offsets[i0] = excl;      g_cursor[i0] = excl; }
    if (i1 < N_NODES) { g_offsets[i1] = excl + a0; g_cursor[i1] = excl + a0; }
    if (t == 1023) g_offsets[N_NODES] = sb[1023];
}
__global__ void k_scatter(const int* __restrict__ dst) {
    int e = blockIdx.x*blockDim.x + threadIdx.x;
    if (e < N_EDGES) {
        int d = dst[e];
        int pos = atomicAdd(&g_cursor[d], 1);
        g_sorted[pos] = e;
    }
}
__global__ void k_binsort() {
    int d = blockIdx.x*blockDim.x + threadIdx.x;
    if (d >= N_NODES) return;
    int s = g_offsets[d], e = g_offsets[d+1];
    for (int i = s + 1; i < e; i++) {
        int key = g_sorted[i];
        int j = i - 1;
        while (j >= s && g_sorted[j] > key) { g_sorted[j+1] = g_sorted[j]; j--; }
        g_sorted[j+1] = key;
    }
}

// ---------------- K4: one warp per (dst,b); cp.async double-buffered ----------------
__global__ void __launch_bounds__(32) k_main(const int* __restrict__ src,
                                             const float* __restrict__ W_out,
                                             const float* __restrict__ b_out,
                                             float* __restrict__ out) {
    int nbd = blockIdx.x;
    int n = nbd >> 2, b = nbd & 3;
    __shared__ __align__(16) float B1d[1024];        // [k][h] dst, fixed
    __shared__ __align__(16) float A2b[2][1024];     // [k][h] src, double-buffered
    __shared__ __align__(16) float stds[12*33];      // std_[l][k], bcast-padded (fixed)
    __shared__ __align__(16) float stsS[2][12*36];   // sts[l][k], double-buffered
    __shared__ __align__(16) float P1s[2][12*36];
    __shared__ __align__(16) float P4m[12*36];       // P4d + mbd (fixed)
    __shared__ __align__(16) float mbsS[2][32];
    __shared__ __align__(16) float wout[512];
    __shared__ __align__(16) float news[384];
    __shared__ int slist[MAXDEG];
    int lane = threadIdx.x;
    int lg = lane >> 3, hg = lane & 7, h4 = hg * 4;
    int l0 = lg * 3;

    int es = g_offsets[n], ee = g_offsets[n+1];
    int deg = ee - es;

    // src-node list (breaks dependent-load chain out of the prefetch path)
    for (int i = lane; i < deg && i < MAXDEG; i += 32)
        slist[i] = src[g_sorted[es + i]];

    // prologue: dst-side fixed data
    {
        const float4* pb = (const float4*)&g_Bm[nbd*2048];
        float4* sbp = (float4*)B1d;
        #pragma unroll
        for (int i = lane; i < 256; i += 32) sbp[i] = pb[i];
        for (int i = lane; i < 384; i += 32) {
            int l = i >> 5, k = i & 31;
            stds[l*33 + k] = g_state[nbd*384 + i];
            P4m[l*36 + k] = g_P4[nbd*384 + i] + g_mbd[nbd*32 + k];
        }
        #pragma unroll
        for (int i = lane; i < 128; i += 32)
            ((float4*)wout)[i] = ((const float4*)W_out)[i];
    }
    __syncwarp();

    u32 sA2[2], sSt[2], sP1[2], sMb[2];
    #pragma unroll
    for (int v = 0; v < 2; v++) {
        sA2[v] = (u32)__cvta_generic_to_shared(&A2b[v][0]);
        sSt[v] = (u32)__cvta_generic_to_shared(&stsS[v][0]);
        sP1[v] = (u32)__cvta_generic_to_shared(&P1s[v][0]);
        sMb[v] = (u32)__cvta_generic_to_shared(&mbsS[v][0]);
    }

    u64 num[3][2], den[3][2];
    #pragma unroll
    for (int j = 0; j < 3; j++) { num[j][0]=num[j][1]=den[j][0]=den[j][1]=0ull; }

    // prefetch lambda: stage src-side operands for edge index i (in-bin) into buf v
    auto prefetch = [&](int i, int v) {
        int nbs = ((i < MAXDEG) ? slist[i] : src[g_sorted[es + i]]) * 4 + b;
        const float* pa = &g_A[nbs*2048 + 1024];
        #pragma unroll
        for (int r = 0; r < 8; r++) {
            int c = lane + 32*r;
            cpa16(sA2[v] + c*16, pa + c*4);
        }
        const float* ps = &g_state[nbs*384];
        const float* pp = &g_P1[nbs*384];
        #pragma unroll
        for (int r = 0; r < 3; r++) {
            int c = lane + 32*r;
            int l = c >> 3, c4 = (c & 7) * 4;
            u32 off = (l*36 + c4) * 4;
            cpa16(sSt[v] + off, ps + c*4);
            cpa16(sP1[v] + off, pp + c*4);
        }
        if (lane < 8) cpa16(sMb[v] + lane*16, &g_mbs[nbs*32 + lane*4]);
    };

    if (deg > 0) { prefetch(0, 0); cpcommit(); }

    for (int i = 0; i < deg; i++) {
        int v = i & 1;
        if (i + 1 < deg) {
            prefetch(i + 1, v ^ 1);
            cpcommit();
            cpwait<1>();
        } else {
            cpwait<0>();
        }
        __syncwarp();

        u64 att[3][2];
        float4 mb4 = *(float4*)&mbsS[v][h4];
        #pragma unroll
        for (int j = 0; j < 3; j++) {
            int l = l0 + j;
            float4 p1 = *(float4*)&P1s[v][l*36 + h4];
            float4 p4 = *(float4*)&P4m[l*36 + h4];
            att[j][0] = pk2(p1.x + p4.x + mb4.x, p1.y + p4.y + mb4.y);
            att[j][1] = pk2(p1.z + p4.z + mb4.z, p1.w + p4.w + mb4.w);
        }
        #pragma unroll 16
        for (int k = 0; k < 32; k++) {
            ulonglong2 bb = *(const ulonglong2*)&B1d[k*32 + h4];
            ulonglong2 aa = *(const ulonglong2*)&A2b[v][k*32 + h4];
            #pragma unroll
            for (int j = 0; j < 3; j++) {
                int l = l0 + j;
                u64 ss = pk2s(stsS[v][l*36 + k]);
                u64 dd = pk2s(stds[l*33 + k]);
                att[j][0] = fma2(ss, bb.x, att[j][0]);
                att[j][1] = fma2(ss, bb.y, att[j][1]);
                att[j][0] = fma2(dd, aa.x, att[j][0]);
                att[j][1] = fma2(dd, aa.y, att[j][1]);
            }
        }
        #pragma unroll
        for (int j = 0; j < 3; j++) {
            int l = l0 + j;
            float a0,a1,a2,a3;
            upk2(a0, a1, att[j][0]); upk2(a2, a3, att[j][1]);
            float e0 = __expf(a0), e1 = __expf(a1), e2 = __expf(a2), e3 = __expf(a3);
            u64 ep0 = pk2(e0, e1), ep1 = pk2(e2, e3);
            den[j][0] = add2(den[j][0], ep0);
            den[j][1] = add2(den[j][1], ep1);
            float4 sv = *(float4*)&stsS[v][l*36 + h4];
            num[j][0] = fma2(ep0, pk2(sv.x, sv.y), num[j][0]);
            num[j][1] = fma2(ep1, pk2(sv.z, sv.w), num[j][1]);
        }
        __syncwarp();
    }

    // news = num / den  (den==0 -> 0, matching reference's empty-mailbox path)
    #pragma unroll
    for (int j = 0; j < 3; j++) {
        int l = l0 + j;
        float n0,n1,n2,n3,d0,d1,d2,d3;
        upk2(n0, n1, num[j][0]); upk2(n2, n3, num[j][1]);
        upk2(d0, d1, den[j][0]); upk2(d2, d3, den[j][1]);
        float4 r;
        r.x = __fdividef(n0, d0 == 0.f ? 1.f : d0);
        r.y = __fdividef(n1, d1 == 0.f ? 1.f : d1);
        r.z = __fdividef(n2, d2 == 0.f ? 1.f : d2);
        r.w = __fdividef(n3, d3 == 0.f ? 1.f : d3);
        *(float4*)&news[l*32 + h4] = r;
    }
    __syncwarp();

    // output projection: 12x16 = 192 outputs, 6 per lane
    for (int oi = lane; oi < L1D*OUTD; oi += 32) {
        int l = oi >> 4, o = oi & 15;
        float acc = b_out[o];
        #pragma unroll
        for (int h = 0; h < HID; h++)
            acc = fmaf(news[l*32 + h], wout[h*16 + o], acc);
        out[((b*L1D + l)*N_NODES + n)*OUTD + o] = acc;
    }
}

// ---------------- launch ----------------
extern "C" void kernel_launch(void* const* d_in, const int* in_sizes, int n_in,
                              void* d_out, int out_size) {
    const float* long_states = (const float*)d_in[0];   // [B,N,REF]
    const float* short_in    = (const float*)d_in[1];   // [B,L1,N,IN]
    const int*   src         = (const int*)d_in[2];
    const int*   dst         = (const int*)d_in[3];
    const float* W_in        = (const float*)d_in[4];
    const float* b_in        = (const float*)d_in[5];
    const float* W_metaW     = (const float*)d_in[6];
    const float* b_metaW     = (const float*)d_in[7];
    const float* W_metab     = (const float*)d_in[8];
    const float* b_metab     = (const float*)d_in[9];
    const float* W_out       = (const float*)d_in[10];
    const float* b_out       = (const float*)d_in[11];
    float* out = (float*)d_out;

    k_state<<<N_NODES, 256>>>(short_in, W_in, b_in);   // also zeroes g_counts
    k_hist<<<(N_EDGES + 255)/256, 256>>>(dst);
    k_meta<<<dim3(NB/32, 2048/128), 128>>>(long_states, W_metaW, b_metaW);
    k_scan<<<1, 1024>>>();
    k_scatter<<<(N_EDGES + 255)/256, 256>>>(dst);
    k_pmb<<<NB, 128>>>(long_states, W_metab, b_metab);
    k_binsort<<<(N_NODES + 255)/256, 256>>>();
    k_main<<<NB, 32>>>(src, W_out, b_out, out);
}